// round 12
// baseline (speedup 1.0000x reference)
#include <cuda_runtime.h>
#include <cuda_fp16.h>
#include <cstdint>
#include <math.h>

#define NE 32
#define TOPK 4
#define HD 2048
#define ID 1024
#define NT 4096
#define MAXP (NT*TOPK)

// ---------------- scratch (static device globals) ----------------
__device__ int      d_counts[NE];
__device__ int      d_perm_tok[NE*NT];
__device__ float    d_perm_w[NE*NT];
__device__ uint32_t d_xh[NT*HD/2];                     // fp16x2, 16MB
__device__ uint32_t d_w13h[(size_t)NE*2*ID*HD/2];      // 256MB
__device__ uint32_t d_w2h[(size_t)NE*HD*ID/2];         // 128MB
__device__ uint32_t d_hh[(size_t)MAXP*ID/2];           // 32MB

// ---------------- helpers ----------------
__device__ __forceinline__ uint32_t smem_u32(const void* p) {
    uint32_t a;
    asm("{ .reg .u64 t; cvta.to.shared.u64 t, %1; cvt.u32.u64 %0, t; }" : "=r"(a) : "l"(p));
    return a;
}
__device__ __forceinline__ uint32_t f2h2(float lo, float hi) {
    uint32_t r;
    asm("cvt.rn.f16x2.f32 %0, %1, %2;" : "=r"(r) : "f"(hi), "f"(lo));
    return r;
}
__device__ __forceinline__ void cpa16(uint32_t dst, const void* src, uint32_t sz) {
    asm volatile("cp.async.cg.shared.global [%0], [%1], 16, %2;"
                 :: "r"(dst), "l"(src), "r"(sz) : "memory");
}
__device__ __forceinline__ void cpa_commit() {
    asm volatile("cp.async.commit_group;" ::: "memory");
}
__device__ __forceinline__ void cpa_wait1() {
    asm volatile("cp.async.wait_group 1;" ::: "memory");
}
__device__ __forceinline__ void ldsm4(uint32_t (&r)[4], uint32_t a) {
    asm volatile("ldmatrix.sync.aligned.m8n8.x4.shared.b16 {%0,%1,%2,%3}, [%4];"
                 : "=r"(r[0]), "=r"(r[1]), "=r"(r[2]), "=r"(r[3]) : "r"(a));
}
__device__ __forceinline__ void mma16816(float (&d)[4], const uint32_t (&a)[4],
                                         uint32_t b0, uint32_t b1) {
    asm volatile("mma.sync.aligned.m16n8k16.row.col.f32.f16.f16.f32 "
                 "{%0,%1,%2,%3}, {%4,%5,%6,%7}, {%8,%9}, {%0,%1,%2,%3};"
                 : "+f"(d[0]), "+f"(d[1]), "+f"(d[2]), "+f"(d[3])
                 : "r"(a[0]), "r"(a[1]), "r"(a[2]), "r"(a[3]), "r"(b0), "r"(b1));
}

// per-block expert base = exclusive prefix of d_counts
__device__ __forceinline__ int expert_base(int e) {
    int base = 0;
    #pragma unroll
    for (int i = 0; i < NE; i++) base += (i < e) ? d_counts[i] : 0;
    return base;
}

// ---------------- smem geometry ----------------
#define STAGES 3
#define CHB 16384                 // one tile: 128 rows x 128B (64 fp16)
#define STG_B (2*CHB)             // A + B tiles per stage
#define SM_G1 (STAGES*STG_B)              // 98304
#define SM_G2 (STAGES*STG_B + 1024)       // + cw/tok arrays

// ============================================================
// zero: out := 0 (harness poisons it), d_counts := 0 (router needs it)
// ============================================================
__global__ void zero_kernel(float4* __restrict__ out) {
    int i = blockIdx.x * blockDim.x + threadIdx.x;
    int stride = gridDim.x * blockDim.x;
    const int n = NT * HD / 4;
    float4 z = make_float4(0.f, 0.f, 0.f, 0.f);
    for (; i < n; i += stride) out[i] = z;
    if (blockIdx.x == 0 && threadIdx.x < NE) d_counts[threadIdx.x] = 0;
}

// ============================================================
// fp32 -> fp16, 32 values (4 uint4 outputs) per thread, batched loads (MLP=8)
__global__ void conv_kernel(const float4* __restrict__ src, uint4* __restrict__ dst, int n8) {
    int i0 = (blockIdx.x * blockDim.x + threadIdx.x) * 4;
    int stride = gridDim.x * blockDim.x * 4;
    for (int i = i0; i < n8; i += stride) {
        float4 a[8];
        #pragma unroll
        for (int j = 0; j < 4; j++) {
            a[2*j]   = src[2*(i+j)];
            a[2*j+1] = src[2*(i+j)+1];
        }
        #pragma unroll
        for (int j = 0; j < 4; j++) {
            dst[i+j] = make_uint4(f2h2(a[2*j].x,   a[2*j].y),
                                  f2h2(a[2*j].z,   a[2*j].w),
                                  f2h2(a[2*j+1].x, a[2*j+1].y),
                                  f2h2(a[2*j+1].z, a[2*j+1].w));
        }
    }
}

// ============================================================
// router: tiled 16-token x 32-expert fp32 GEMM (256 blocks -> ~2/SM)
// + sigmoid/top-4/renorm/scatter. x->fp16 conversion fused.
// ============================================================
#define RB 16
__global__ __launch_bounds__(256) void router_kernel(const float* __restrict__ x,
                              const float* __restrict__ gw,
                              const float* __restrict__ bias) {
    __shared__ float xs[RB][64];
    __shared__ float gs[64][32];
    __shared__ float lg[RB][33];

    int tid = threadIdx.x;
    int t0 = blockIdx.x * RB;
    int r  = tid >> 3;                 // 0..31 (gw row); x row for tid<128
    int c8 = (tid & 7) * 8;

    int e  = tid & 31;                 // compute: expert
    int tg = tid >> 5;                 // compute: token group (0..7)

    float acc0 = 0.f, acc1 = 0.f;

    for (int k0 = 0; k0 < HD; k0 += 64) {
        if (tid < 128) {               // x tile: 16 rows x 64 cols (+ fused conv)
            const float4* p = (const float4*)(x + (size_t)(t0 + r) * HD + k0 + c8);
            float4 a = p[0], b = p[1];
            xs[r][c8+0] = a.x; xs[r][c8+1] = a.y; xs[r][c8+2] = a.z; xs[r][c8+3] = a.w;
            xs[r][c8+4] = b.x; xs[r][c8+5] = b.y; xs[r][c8+6] = b.z; xs[r][c8+7] = b.w;
            ((uint4*)d_xh)[(size_t)(t0 + r) * (HD/8) + (k0 + c8) / 8] =
                make_uint4(f2h2(a.x,a.y), f2h2(a.z,a.w), f2h2(b.x,b.y), f2h2(b.z,b.w));
        }
        {                              // gw tile transposed to k-major
            const float4* p = (const float4*)(gw + (size_t)r * HD + k0 + c8);
            float4 a = p[0], b = p[1];
            gs[c8+0][r] = a.x; gs[c8+1][r] = a.y; gs[c8+2][r] = a.z; gs[c8+3][r] = a.w;
            gs[c8+4][r] = b.x; gs[c8+5][r] = b.y; gs[c8+6][r] = b.z; gs[c8+7][r] = b.w;
        }
        __syncthreads();
        #pragma unroll
        for (int k = 0; k < 64; k++) {
            float g = gs[k][e];
            acc0 = fmaf(xs[tg    ][k], g, acc0);
            acc1 = fmaf(xs[tg + 8][k], g, acc1);
        }
        __syncthreads();
    }
    lg[tg    ][e] = acc0;
    lg[tg + 8][e] = acc1;
    __syncthreads();

    if (tid < RB) {
        int t = t0 + tid;
        float sc[NE], bs[NE];
        #pragma unroll
        for (int i = 0; i < NE; i++) {
            float v = 1.f / (1.f + expf(-lg[tid][i]));
            sc[i] = v;
            bs[i] = v + bias[i];
        }
        int idx[TOPK]; float w[TOPK]; float sum = 0.f;
        #pragma unroll
        for (int k = 0; k < TOPK; k++) {
            int bi = 0; float bv = -1e30f;
            #pragma unroll
            for (int i = 0; i < NE; i++)
                if (bs[i] > bv) { bv = bs[i]; bi = i; }
            bs[bi] = -1e30f;
            idx[k] = bi; w[k] = sc[bi]; sum += sc[bi];
        }
        float inv = 1.f / sum;
        #pragma unroll
        for (int k = 0; k < TOPK; k++) {
            int ex = idx[k];
            int pos = atomicAdd(&d_counts[ex], 1);
            d_perm_tok[ex * NT + pos] = t;
            d_perm_w[ex * NT + pos]   = w[k] * inv;
        }
    }
}

// ============================================================
// GEMM1: gu = x_e @ w13_e^T (fp16 mma), fused SwiGLU epilogue -> d_hh (fp16)
// 256 threads, 8 warps (2x4), warp tile 64x32, 3-stage cp.async,
// single-sync mainloop (R5 schedule).
// ============================================================
__global__ __launch_bounds__(256, 2) void gemm1_mma() {
    int e = blockIdx.z;
    int cnt = d_counts[e];
    int m0 = blockIdx.y * 128;
    if (m0 >= cnt) return;
    int jj = blockIdx.x;                 // h-column block of 64
    int base = expert_base(e);

    extern __shared__ char sm[];
    uint32_t sb = smem_u32(sm);
    int tid = threadIdx.x;

    int fr = tid >> 1;
    int fs = (tid & 1) * 64;
    uint32_t fkey = (uint32_t)((fr & 7) << 4);
    uint32_t fdst = (uint32_t)(fr * 128);
    bool av = (m0 + fr) < cnt;
    const char* aSrc = (const char*)d_xh;
    if (av) aSrc += ((size_t)d_perm_tok[e * NT + m0 + fr] * HD) * 2 + fs;
    int wrow = ((fr & 1) ? ID : 0) + jj * 64 + (fr >> 1);   // interleave gate/up
    const char* bSrc = (const char*)d_w13h + ((size_t)(e * 2 * ID) + wrow) * HD * 2 + fs;

    int l = tid & 31, w = tid >> 5;
    int wm = w & 1, wn = w >> 1;
    uint32_t key = (uint32_t)((l & 7) << 4);
    uint32_t c0  = (uint32_t)((l >> 4) * 16);
    uint32_t aBase = (uint32_t)((wm * 64 + (l & 15)) * 128);
    uint32_t bBase = (uint32_t)(CHB + (wn * 32 + (l & 15)) * 128);

    float d[4][4][4];
    #pragma unroll
    for (int i = 0; i < 4; i++)
        #pragma unroll
        for (int j = 0; j < 4; j++)
            #pragma unroll
            for (int q = 0; q < 4; q++) d[i][j][q] = 0.f;

    const int NC = HD / 64;   // 32

    // prologue: fill chunks 0,1
    #pragma unroll
    for (int s = 0; s < 2; s++) {
        uint32_t s0 = sb + s * STG_B;
        const char* as = aSrc + s * 128;
        const char* bs = bSrc + s * 128;
        #pragma unroll
        for (int i = 0; i < 4; i++) {
            uint32_t so = (uint32_t)(fs + i * 16) ^ fkey;
            cpa16(s0 + fdst + so, as + i * 16, av ? 16 : 0);
            cpa16(s0 + CHB + fdst + so, bs + i * 16, 16);
        }
        cpa_commit();
    }

    for (int c = 0; c < NC; c++) {
        cpa_wait1();                 // fill(c) complete
        __syncthreads();             // also: all warps done with mma(c-1)
        int nc = c + 2;
        if (nc < NC) {
            uint32_t sf = sb + (nc % STAGES) * STG_B;   // buffer consumed at c-1
            const char* as = aSrc + nc * 128;
            const char* bs = bSrc + nc * 128;
            #pragma unroll
            for (int i = 0; i < 4; i++) {
                uint32_t so = (uint32_t)(fs + i * 16) ^ fkey;
                cpa16(sf + fdst + so, as + i * 16, av ? 16 : 0);
                cpa16(sf + CHB + fdst + so, bs + i * 16, 16);
            }
        }
        cpa_commit();
        uint32_t s0 = sb + (c % STAGES) * STG_B;
        #pragma unroll
        for (int ks = 0; ks < 4; ks++) {
            uint32_t kb = (uint32_t)(ks * 32);
            uint32_t a[4][4], bfr[2][4];
            #pragma unroll
            for (int mb = 0; mb < 4; mb++)
                ldsm4(a[mb], s0 + aBase + mb * 2048 + ((kb + c0) ^ key));
            #pragma unroll
            for (int nb2 = 0; nb2 < 2; nb2++)
                ldsm4(bfr[nb2], s0 + bBase + nb2 * 2048 + ((kb + c0) ^ key));
            #pragma unroll
            for (int mb = 0; mb < 4; mb++)
                #pragma unroll
                for (int n = 0; n < 4; n++)
                    mma16816(d[mb][n], a[mb], bfr[n >> 1][n & 1], bfr[n >> 1][(n & 1) + 2]);
        }
    }
    __syncthreads();

    __half* smh = (__half*)sm;     // 128 x 64 fp16 = 16KB (stage0 reuse, all mma done)
    int rbase = wm * 64 + (l >> 2);
    int tcol  = wn * 16 + (l & 3);
    #pragma unroll
    for (int mb = 0; mb < 4; mb++) {
        int r0 = rbase + mb * 16;
        #pragma unroll
        for (int nb = 0; nb < 4; nb++) {
            int tc = tcol + nb * 4;
            float g0 = d[mb][nb][0], u0 = d[mb][nb][1];
            float g1 = d[mb][nb][2], u1 = d[mb][nb][3];
            float h0 = g0 / (1.f + __expf(-g0)) * u0;
            float h1 = g1 / (1.f + __expf(-g1)) * u1;
            smh[r0 * 64 + tc]       = __float2half(h0);
            smh[(r0 + 8) * 64 + tc] = __float2half(h1);
        }
    }
    __syncthreads();
    int rr = tid >> 1;
    int hh = (tid & 1) * 32;
    if ((m0 + rr) < cnt) {
        const uint4* s4 = (const uint4*)((const char*)sm + (rr * 64 + hh) * 2);
        uint4* g4 = (uint4*)((char*)d_hh + (((size_t)(base + m0 + rr)) * ID + jj * 64 + hh) * 2);
        g4[0] = s4[0]; g4[1] = s4[1]; g4[2] = s4[2]; g4[3] = s4[3];
    }
}

// ============================================================
// GEMM2: y = h_e @ w2_e^T (fp16 mma); epilogue: out[tok] += cw*y via RED.
// Same single-sync mainloop.
// ============================================================
__global__ __launch_bounds__(256, 2) void gemm2_mma(float* __restrict__ out) {
    int e = blockIdx.z;
    int cnt = d_counts[e];
    int m0 = blockIdx.y * 128;
    if (m0 >= cnt) return;
    int n0 = blockIdx.x * 128;
    int base = expert_base(e);

    extern __shared__ char sm[];
    uint32_t sb = smem_u32(sm);
    int tid = threadIdx.x;

    float* s_cw = (float*)(sm + STAGES * STG_B);
    int*   s_tk = (int*)(sm + STAGES * STG_B + 512);
    if (tid < 128) {
        int m = m0 + tid;
        if (m < cnt) {
            s_cw[tid] = d_perm_w[e * NT + m];
            s_tk[tid] = d_perm_tok[e * NT + m];
        }
    }

    int fr = tid >> 1;
    int fs = (tid & 1) * 64;
    uint32_t fkey = (uint32_t)((fr & 7) << 4);
    uint32_t fdst = (uint32_t)(fr * 128);
    bool av = (m0 + fr) < cnt;
    const char* aSrc = (const char*)d_hh;
    if (av) aSrc += ((size_t)(base + m0 + fr) * ID) * 2 + fs;
    const char* bSrc = (const char*)d_w2h + ((size_t)(e * HD) + n0 + fr) * ID * 2 + fs;

    int l = tid & 31, w = tid >> 5;
    int wm = w & 1, wn = w >> 1;
    uint32_t key = (uint32_t)((l & 7) << 4);
    uint32_t c0  = (uint32_t)((l >> 4) * 16);
    uint32_t aBase = (uint32_t)((wm * 64 + (l & 15)) * 128);
    uint32_t bBase = (uint32_t)(CHB + (wn * 32 + (l & 15)) * 128);

    float d[4][4][4];
    #pragma unroll
    for (int i = 0; i < 4; i++)
        #pragma unroll
        for (int j = 0; j < 4; j++)
            #pragma unroll
            for (int q = 0; q < 4; q++) d[i][j][q] = 0.f;

    const int NC = ID / 64;   // 16

    #pragma unroll
    for (int s = 0; s < 2; s++) {
        uint32_t s0 = sb + s * STG_B;
        const char* as = aSrc + s * 128;
        const char* bs = bSrc + s * 128;
        #pragma unroll
        for (int i = 0; i < 4; i++) {
            uint32_t so = (uint32_t)(fs + i * 16) ^ fkey;
            cpa16(s0 + fdst + so, as + i * 16, av ? 16 : 0);
            cpa16(s0 + CHB + fdst + so, bs + i * 16, 16);
        }
        cpa_commit();
    }

    for (int c = 0; c < NC; c++) {
        cpa_wait1();
        __syncthreads();
        int nc = c + 2;
        if (nc < NC) {
            uint32_t sf = sb + (nc % STAGES) * STG_B;
            const char* as = aSrc + nc * 128;
            const char* bs = bSrc + nc * 128;
            #pragma unroll
            for (int i = 0; i < 4; i++) {
                uint32_t so = (uint32_t)(fs + i * 16) ^ fkey;
                cpa16(sf + fdst + so, as + i * 16, av ? 16 : 0);
                cpa16(sf + CHB + fdst + so, bs + i * 16, 16);
            }
        }
        cpa_commit();
        uint32_t s0 = sb + (c % STAGES) * STG_B;
        #pragma unroll
        for (int ks = 0; ks < 4; ks++) {
            uint32_t kb = (uint32_t)(ks * 32);
            uint32_t a[4][4], bfr[2][4];
            #pragma unroll
            for (int mb = 0; mb < 4; mb++)
                ldsm4(a[mb], s0 + aBase + mb * 2048 + ((kb + c0) ^ key));
            #pragma unroll
            for (int nb2 = 0; nb2 < 2; nb2++)
                ldsm4(bfr[nb2], s0 + bBase + nb2 * 2048 + ((kb + c0) ^ key));
            #pragma unroll
            for (int mb = 0; mb < 4; mb++)
                #pragma unroll
                for (int n = 0; n < 4; n++)
                    mma16816(d[mb][n], a[mb], bfr[n >> 1][n & 1], bfr[n >> 1][(n & 1) + 2]);
        }
    }

    // ---- epilogue: out[tok][col] += cw * y  (RED.F32, combine fused) ----
    int rbase = wm * 64 + (l >> 2);
    int cb = n0 + wn * 32 + 2 * (l & 3);
    #pragma unroll
    for (int mb = 0; mb < 4; mb++) {
        int r0 = rbase + mb * 16;
        int r1 = r0 + 8;
        bool v0 = (m0 + r0) < cnt;
        bool v1 = (m0 + r1) < cnt;
        float cw0 = v0 ? s_cw[r0] : 0.f;
        float cw1 = v1 ? s_cw[r1] : 0.f;
        float* o0 = v0 ? (out + (size_t)s_tk[r0] * HD) : out;
        float* o1 = v1 ? (out + (size_t)s_tk[r1] * HD) : out;
        #pragma unroll
        for (int nb = 0; nb < 4; nb++) {
            int col = cb + nb * 8;
            if (v0) {
                atomicAdd(&o0[col],     cw0 * d[mb][nb][0]);
                atomicAdd(&o0[col + 1], cw0 * d[mb][nb][1]);
            }
            if (v1) {
                atomicAdd(&o1[col],     cw1 * d[mb][nb][2]);
                atomicAdd(&o1[col + 1], cw1 * d[mb][nb][3]);
            }
        }
    }
}

// ============================================================
extern "C" void kernel_launch(void* const* d_in, const int* in_sizes, int n_in,
                              void* d_out, int out_size) {
    const float* x    = (const float*)d_in[0];   // [T, H]
    const float* gw   = (const float*)d_in[1];   // [E, H]
    const float* bias = (const float*)d_in[2];   // [E]
    const float* w13  = (const float*)d_in[3];   // [E, 2I, H]
    const float* w2   = (const float*)d_in[4];   // [E, H, I]
    float* out = (float*)d_out;                  // [T, H]

    static int inited = 0;
    if (!inited) {
        cudaFuncSetAttribute(gemm1_mma, cudaFuncAttributeMaxDynamicSharedMemorySize, SM_G1);
        cudaFuncSetAttribute(gemm2_mma, cudaFuncAttributeMaxDynamicSharedMemorySize, SM_G2);
        inited = 1;
    }

    uint4* w13h_p; cudaGetSymbolAddress((void**)&w13h_p, d_w13h);
    uint4* w2h_p;  cudaGetSymbolAddress((void**)&w2h_p,  d_w2h);

    // 1: zero out + counts
    zero_kernel<<<2048, 256>>>((float4*)out);

    // 2,3: weight conversions
    conv_kernel<<<(NE*2*ID*(HD/8))/4/256, 256>>>((const float4*)w13, (uint4*)w13h_p, NE * 2 * ID * (HD / 8));
    conv_kernel<<<(NE*HD*(ID/8))/4/256,   256>>>((const float4*)w2,  (uint4*)w2h_p,  NE * HD * (ID / 8));

    // 4: router (tiled; also converts x -> d_xh)
    router_kernel<<<NT/RB, 256>>>(x, gw, bias);

    // 5: gemm1
    dim3 g1(ID / 64, NT / 128, NE);      // (16, 32, 32)
    gemm1_mma<<<g1, 256, SM_G1>>>();

    // 6: gemm2 (combine fused via RED)
    dim3 g2(HD / 128, NT / 128, NE);     // (16, 32, 32)
    gemm2_mma<<<g2, 256, SM_G2>>>(out);
}

// round 13
// speedup vs baseline: 1.0137x; 1.0137x over previous
#include <cuda_runtime.h>
#include <cuda_fp16.h>
#include <cstdint>
#include <math.h>

#define NE 32
#define TOPK 4
#define HD 2048
#define ID 1024
#define NT 4096
#define MAXP (NT*TOPK)
#define KSLICES 4
#define KSL (HD/KSLICES)          // 512

// ---------------- scratch (static device globals) ----------------
__device__ int      d_counts[NE];
__device__ int      d_perm_tok[NE*NT];
__device__ float    d_perm_w[NE*NT];
__device__ float    d_lgpart[KSLICES*NT*NE];           // split-K partial logits, 2MB
__device__ uint32_t d_xh[NT*HD/2];                     // fp16x2, 16MB
__device__ uint32_t d_w13h[(size_t)NE*2*ID*HD/2];      // 256MB
__device__ uint32_t d_w2h[(size_t)NE*HD*ID/2];         // 128MB
__device__ uint32_t d_hh[(size_t)MAXP*ID/2];           // 32MB

// ---------------- helpers ----------------
__device__ __forceinline__ uint32_t smem_u32(const void* p) {
    uint32_t a;
    asm("{ .reg .u64 t; cvta.to.shared.u64 t, %1; cvt.u32.u64 %0, t; }" : "=r"(a) : "l"(p));
    return a;
}
__device__ __forceinline__ uint32_t f2h2(float lo, float hi) {
    uint32_t r;
    asm("cvt.rn.f16x2.f32 %0, %1, %2;" : "=r"(r) : "f"(hi), "f"(lo));
    return r;
}
__device__ __forceinline__ void cpa16(uint32_t dst, const void* src, uint32_t sz) {
    asm volatile("cp.async.cg.shared.global [%0], [%1], 16, %2;"
                 :: "r"(dst), "l"(src), "r"(sz) : "memory");
}
__device__ __forceinline__ void cpa_commit() {
    asm volatile("cp.async.commit_group;" ::: "memory");
}
__device__ __forceinline__ void cpa_wait2() {
    asm volatile("cp.async.wait_group 2;" ::: "memory");
}
__device__ __forceinline__ void ldsm4(uint32_t (&r)[4], uint32_t a) {
    asm volatile("ldmatrix.sync.aligned.m8n8.x4.shared.b16 {%0,%1,%2,%3}, [%4];"
                 : "=r"(r[0]), "=r"(r[1]), "=r"(r[2]), "=r"(r[3]) : "r"(a));
}
__device__ __forceinline__ void mma16816(float (&d)[4], const uint32_t (&a)[4],
                                         uint32_t b0, uint32_t b1) {
    asm volatile("mma.sync.aligned.m16n8k16.row.col.f32.f16.f16.f32 "
                 "{%0,%1,%2,%3}, {%4,%5,%6,%7}, {%8,%9}, {%0,%1,%2,%3};"
                 : "+f"(d[0]), "+f"(d[1]), "+f"(d[2]), "+f"(d[3])
                 : "r"(a[0]), "r"(a[1]), "r"(a[2]), "r"(a[3]), "r"(b0), "r"(b1));
}

// per-block expert base = exclusive prefix of d_counts
__device__ __forceinline__ int expert_base(int e) {
    int base = 0;
    #pragma unroll
    for (int i = 0; i < NE; i++) base += (i < e) ? d_counts[i] : 0;
    return base;
}

// ---------------- smem geometry ----------------
#define STAGES 3
#define CHB 16384                 // one tile: 128 rows x 128B (64 fp16)
#define STG_B (2*CHB)             // A + B tiles per stage
#define SM_G1 (STAGES*STG_B)              // 98304
#define SM_G2 (STAGES*STG_B + 1024)       // + cw/tok arrays

// ============================================================
// zero: out := 0 (harness poisons it), d_counts := 0
// ============================================================
__global__ void zero_kernel(float4* __restrict__ out) {
    int i = blockIdx.x * blockDim.x + threadIdx.x;
    int stride = gridDim.x * blockDim.x;
    const int n = NT * HD / 4;
    float4 z = make_float4(0.f, 0.f, 0.f, 0.f);
    for (; i < n; i += stride) out[i] = z;
    if (blockIdx.x == 0 && threadIdx.x < NE) d_counts[threadIdx.x] = 0;
}

// ============================================================
// fp32 -> fp16, 32 values (4 uint4 outputs) per thread, batched loads (MLP=8)
__global__ void conv_kernel(const float4* __restrict__ src, uint4* __restrict__ dst, int n8) {
    int i0 = (blockIdx.x * blockDim.x + threadIdx.x) * 4;
    int stride = gridDim.x * blockDim.x * 4;
    for (int i = i0; i < n8; i += stride) {
        float4 a[8];
        #pragma unroll
        for (int j = 0; j < 4; j++) {
            a[2*j]   = src[2*(i+j)];
            a[2*j+1] = src[2*(i+j)+1];
        }
        #pragma unroll
        for (int j = 0; j < 4; j++) {
            dst[i+j] = make_uint4(f2h2(a[2*j].x,   a[2*j].y),
                                  f2h2(a[2*j].z,   a[2*j].w),
                                  f2h2(a[2*j+1].x, a[2*j+1].y),
                                  f2h2(a[2*j+1].z, a[2*j+1].w));
        }
    }
}

// ============================================================
// router stage 1: split-K logits GEMM. grid (NT/32, KSLICES).
// Block (t0, s): partial logits over k in [s*KSL, (s+1)*KSL) for 32 tokens.
// Also converts its x columns to fp16 (fused).
// ============================================================
#define RB 32
__global__ __launch_bounds__(256) void router_gemm(const float* __restrict__ x,
                                                   const float* __restrict__ gw) {
    __shared__ float xs[RB][64];
    __shared__ float gs[64][32];

    int tid = threadIdx.x;
    int t0 = blockIdx.x * RB;
    int sl = blockIdx.y;
    int k0s = sl * KSL;
    int r  = tid >> 3;
    int c8 = (tid & 7) * 8;

    int e  = tid & 31;
    int tg = tid >> 5;

    float acc0 = 0.f, acc1 = 0.f, acc2 = 0.f, acc3 = 0.f;

    for (int k0 = k0s; k0 < k0s + KSL; k0 += 64) {
        {
            const float4* p = (const float4*)(x + (size_t)(t0 + r) * HD + k0 + c8);
            float4 a = p[0], b = p[1];
            xs[r][c8+0] = a.x; xs[r][c8+1] = a.y; xs[r][c8+2] = a.z; xs[r][c8+3] = a.w;
            xs[r][c8+4] = b.x; xs[r][c8+5] = b.y; xs[r][c8+6] = b.z; xs[r][c8+7] = b.w;
            ((uint4*)d_xh)[(size_t)(t0 + r) * (HD/8) + (k0 + c8) / 8] =
                make_uint4(f2h2(a.x,a.y), f2h2(a.z,a.w), f2h2(b.x,b.y), f2h2(b.z,b.w));
        }
        {
            const float4* p = (const float4*)(gw + (size_t)r * HD + k0 + c8);
            float4 a = p[0], b = p[1];
            gs[c8+0][r] = a.x; gs[c8+1][r] = a.y; gs[c8+2][r] = a.z; gs[c8+3][r] = a.w;
            gs[c8+4][r] = b.x; gs[c8+5][r] = b.y; gs[c8+6][r] = b.z; gs[c8+7][r] = b.w;
        }
        __syncthreads();
        #pragma unroll
        for (int k = 0; k < 64; k++) {
            float g = gs[k][e];
            acc0 = fmaf(xs[tg     ][k], g, acc0);
            acc1 = fmaf(xs[tg +  8][k], g, acc1);
            acc2 = fmaf(xs[tg + 16][k], g, acc2);
            acc3 = fmaf(xs[tg + 24][k], g, acc3);
        }
        __syncthreads();
    }
    // store partials: [slice][token][expert], coalesced over e
    float* lp = d_lgpart + ((size_t)sl * NT + t0) * NE;
    lp[(tg     ) * NE + e] = acc0;
    lp[(tg +  8) * NE + e] = acc1;
    lp[(tg + 16) * NE + e] = acc2;
    lp[(tg + 24) * NE + e] = acc3;
}

// ============================================================
// router stage 2: sum slices, sigmoid, biased top-4, renorm, scatter.
// one thread per token.
// ============================================================
__global__ __launch_bounds__(256) void topk_kernel(const float* __restrict__ bias) {
    int t = blockIdx.x * blockDim.x + threadIdx.x;
    if (t >= NT) return;
    float sc[NE], bs[NE];
    #pragma unroll
    for (int i = 0; i < NE; i++) {
        float lg = 0.f;
        #pragma unroll
        for (int s = 0; s < KSLICES; s++)
            lg += d_lgpart[((size_t)s * NT + t) * NE + i];
        float v = 1.f / (1.f + expf(-lg));
        sc[i] = v;
        bs[i] = v + bias[i];
    }
    int idx[TOPK]; float w[TOPK]; float sum = 0.f;
    #pragma unroll
    for (int k = 0; k < TOPK; k++) {
        int bi = 0; float bv = -1e30f;
        #pragma unroll
        for (int i = 0; i < NE; i++)
            if (bs[i] > bv) { bv = bs[i]; bi = i; }
        bs[bi] = -1e30f;
        idx[k] = bi; w[k] = sc[bi]; sum += sc[bi];
    }
    float inv = 1.f / sum;
    #pragma unroll
    for (int k = 0; k < TOPK; k++) {
        int ex = idx[k];
        int pos = atomicAdd(&d_counts[ex], 1);
        d_perm_tok[ex * NT + pos] = t;
        d_perm_w[ex * NT + pos]   = w[k] * inv;
    }
}

// ============================================================
// GEMM1: gu = x_e @ w13_e^T (fp16 mma), fused SwiGLU epilogue -> d_hh (fp16)
// 256 threads, 8 warps (2x4), warp tile 64x32, 3-stage cp.async. (R11 frozen)
// ============================================================
__global__ __launch_bounds__(256, 2) void gemm1_mma() {
    int e = blockIdx.z;
    int cnt = d_counts[e];
    int m0 = blockIdx.y * 128;
    if (m0 >= cnt) return;
    int jj = blockIdx.x;                 // h-column block of 64
    int base = expert_base(e);

    extern __shared__ char sm[];
    uint32_t sb = smem_u32(sm);
    int tid = threadIdx.x;

    int fr = tid >> 1;
    int fs = (tid & 1) * 64;
    uint32_t fkey = (uint32_t)((fr & 7) << 4);
    uint32_t fdst = (uint32_t)(fr * 128);
    bool av = (m0 + fr) < cnt;
    const char* aSrc = (const char*)d_xh;
    if (av) aSrc += ((size_t)d_perm_tok[e * NT + m0 + fr] * HD) * 2 + fs;
    int wrow = ((fr & 1) ? ID : 0) + jj * 64 + (fr >> 1);   // interleave gate/up
    const char* bSrc = (const char*)d_w13h + ((size_t)(e * 2 * ID) + wrow) * HD * 2 + fs;

    int l = tid & 31, w = tid >> 5;
    int wm = w & 1, wn = w >> 1;
    uint32_t key = (uint32_t)((l & 7) << 4);
    uint32_t c0  = (uint32_t)((l >> 4) * 16);
    uint32_t aBase = (uint32_t)((wm * 64 + (l & 15)) * 128);
    uint32_t bBase = (uint32_t)(CHB + (wn * 32 + (l & 15)) * 128);

    float d[4][4][4];
    #pragma unroll
    for (int i = 0; i < 4; i++)
        #pragma unroll
        for (int j = 0; j < 4; j++)
            #pragma unroll
            for (int q = 0; q < 4; q++) d[i][j][q] = 0.f;

    const int NC = HD / 64;   // 32

    #pragma unroll
    for (int s = 0; s < STAGES; s++) {
        if (s < NC) {
            uint32_t s0 = sb + s * STG_B;
            const char* as = aSrc + s * 128;
            const char* bs = bSrc + s * 128;
            #pragma unroll
            for (int i = 0; i < 4; i++) {
                uint32_t so = (uint32_t)(fs + i * 16) ^ fkey;
                cpa16(s0 + fdst + so, as + i * 16, av ? 16 : 0);
                cpa16(s0 + CHB + fdst + so, bs + i * 16, 16);
            }
        }
        cpa_commit();
    }

    for (int c = 0; c < NC; c++) {
        cpa_wait2();
        __syncthreads();
        uint32_t s0 = sb + (c % STAGES) * STG_B;
        #pragma unroll
        for (int ks = 0; ks < 4; ks++) {
            uint32_t kb = (uint32_t)(ks * 32);
            uint32_t a[4][4], bfr[2][4];
            #pragma unroll
            for (int mb = 0; mb < 4; mb++)
                ldsm4(a[mb], s0 + aBase + mb * 2048 + ((kb + c0) ^ key));
            #pragma unroll
            for (int nb2 = 0; nb2 < 2; nb2++)
                ldsm4(bfr[nb2], s0 + bBase + nb2 * 2048 + ((kb + c0) ^ key));
            #pragma unroll
            for (int mb = 0; mb < 4; mb++)
                #pragma unroll
                for (int n = 0; n < 4; n++)
                    mma16816(d[mb][n], a[mb], bfr[n >> 1][n & 1], bfr[n >> 1][(n & 1) + 2]);
        }
        __syncthreads();
        int nc = c + STAGES;
        if (nc < NC) {
            uint32_t sf = sb + (c % STAGES) * STG_B;
            const char* as = aSrc + nc * 128;
            const char* bs = bSrc + nc * 128;
            #pragma unroll
            for (int i = 0; i < 4; i++) {
                uint32_t so = (uint32_t)(fs + i * 16) ^ fkey;
                cpa16(sf + fdst + so, as + i * 16, av ? 16 : 0);
                cpa16(sf + CHB + fdst + so, bs + i * 16, 16);
            }
        }
        cpa_commit();
    }

    __half* smh = (__half*)sm;     // 128 x 64 fp16 = 16KB (stage0 reuse, all mma done)
    int rbase = wm * 64 + (l >> 2);
    int tcol  = wn * 16 + (l & 3);
    #pragma unroll
    for (int mb = 0; mb < 4; mb++) {
        int r0 = rbase + mb * 16;
        #pragma unroll
        for (int nb = 0; nb < 4; nb++) {
            int tc = tcol + nb * 4;
            float g0 = d[mb][nb][0], u0 = d[mb][nb][1];
            float g1 = d[mb][nb][2], u1 = d[mb][nb][3];
            float h0 = g0 / (1.f + __expf(-g0)) * u0;
            float h1 = g1 / (1.f + __expf(-g1)) * u1;
            smh[r0 * 64 + tc]       = __float2half(h0);
            smh[(r0 + 8) * 64 + tc] = __float2half(h1);
        }
    }
    __syncthreads();
    int rr = tid >> 1;
    int hh = (tid & 1) * 32;
    if ((m0 + rr) < cnt) {
        const uint4* s4 = (const uint4*)((const char*)sm + (rr * 64 + hh) * 2);
        uint4* g4 = (uint4*)((char*)d_hh + (((size_t)(base + m0 + rr)) * ID + jj * 64 + hh) * 2);
        g4[0] = s4[0]; g4[1] = s4[1]; g4[2] = s4[2]; g4[3] = s4[3];
    }
}

// ============================================================
// GEMM2: y = h_e @ w2_e^T (fp16 mma); epilogue: out[tok] += cw*y via RED. (R11 frozen)
// ============================================================
__global__ __launch_bounds__(256, 2) void gemm2_mma(float* __restrict__ out) {
    int e = blockIdx.z;
    int cnt = d_counts[e];
    int m0 = blockIdx.y * 128;
    if (m0 >= cnt) return;
    int n0 = blockIdx.x * 128;
    int base = expert_base(e);

    extern __shared__ char sm[];
    uint32_t sb = smem_u32(sm);
    int tid = threadIdx.x;

    float* s_cw = (float*)(sm + STAGES * STG_B);
    int*   s_tk = (int*)(sm + STAGES * STG_B + 512);
    if (tid < 128) {
        int m = m0 + tid;
        if (m < cnt) {
            s_cw[tid] = d_perm_w[e * NT + m];
            s_tk[tid] = d_perm_tok[e * NT + m];
        }
    }

    int fr = tid >> 1;
    int fs = (tid & 1) * 64;
    uint32_t fkey = (uint32_t)((fr & 7) << 4);
    uint32_t fdst = (uint32_t)(fr * 128);
    bool av = (m0 + fr) < cnt;
    const char* aSrc = (const char*)d_hh;
    if (av) aSrc += ((size_t)(base + m0 + fr) * ID) * 2 + fs;
    const char* bSrc = (const char*)d_w2h + ((size_t)(e * HD) + n0 + fr) * ID * 2 + fs;

    int l = tid & 31, w = tid >> 5;
    int wm = w & 1, wn = w >> 1;
    uint32_t key = (uint32_t)((l & 7) << 4);
    uint32_t c0  = (uint32_t)((l >> 4) * 16);
    uint32_t aBase = (uint32_t)((wm * 64 + (l & 15)) * 128);
    uint32_t bBase = (uint32_t)(CHB + (wn * 32 + (l & 15)) * 128);

    float d[4][4][4];
    #pragma unroll
    for (int i = 0; i < 4; i++)
        #pragma unroll
        for (int j = 0; j < 4; j++)
            #pragma unroll
            for (int q = 0; q < 4; q++) d[i][j][q] = 0.f;

    const int NC = ID / 64;   // 16

    #pragma unroll
    for (int s = 0; s < STAGES; s++) {
        if (s < NC) {
            uint32_t s0 = sb + s * STG_B;
            const char* as = aSrc + s * 128;
            const char* bs = bSrc + s * 128;
            #pragma unroll
            for (int i = 0; i < 4; i++) {
                uint32_t so = (uint32_t)(fs + i * 16) ^ fkey;
                cpa16(s0 + fdst + so, as + i * 16, av ? 16 : 0);
                cpa16(s0 + CHB + fdst + so, bs + i * 16, 16);
            }
        }
        cpa_commit();
    }

    for (int c = 0; c < NC; c++) {
        cpa_wait2();
        __syncthreads();
        uint32_t s0 = sb + (c % STAGES) * STG_B;
        #pragma unroll
        for (int ks = 0; ks < 4; ks++) {
            uint32_t kb = (uint32_t)(ks * 32);
            uint32_t a[4][4], bfr[2][4];
            #pragma unroll
            for (int mb = 0; mb < 4; mb++)
                ldsm4(a[mb], s0 + aBase + mb * 2048 + ((kb + c0) ^ key));
            #pragma unroll
            for (int nb2 = 0; nb2 < 2; nb2++)
                ldsm4(bfr[nb2], s0 + bBase + nb2 * 2048 + ((kb + c0) ^ key));
            #pragma unroll
            for (int mb = 0; mb < 4; mb++)
                #pragma unroll
                for (int n = 0; n < 4; n++)
                    mma16816(d[mb][n], a[mb], bfr[n >> 1][n & 1], bfr[n >> 1][(n & 1) + 2]);
        }
        __syncthreads();
        int nc = c + STAGES;
        if (nc < NC) {
            uint32_t sf = sb + (c % STAGES) * STG_B;
            const char* as = aSrc + nc * 128;
            const char* bs = bSrc + nc * 128;
            #pragma unroll
            for (int i = 0; i < 4; i++) {
                uint32_t so = (uint32_t)(fs + i * 16) ^ fkey;
                cpa16(sf + fdst + so, as + i * 16, av ? 16 : 0);
                cpa16(sf + CHB + fdst + so, bs + i * 16, 16);
            }
        }
        cpa_commit();
    }

    // ---- epilogue: out[tok][col] += cw * y  (RED.F32, combine fused) ----
    int rbase = wm * 64 + (l >> 2);
    int cb = n0 + wn * 32 + 2 * (l & 3);
    #pragma unroll
    for (int mb = 0; mb < 4; mb++) {
        int r0 = rbase + mb * 16;
        int r1 = r0 + 8;
        bool v0 = (m0 + r0) < cnt;
        bool v1 = (m0 + r1) < cnt;
        float cw0 = v0 ? s_cw[r0] : 0.f;
        float cw1 = v1 ? s_cw[r1] : 0.f;
        float* o0 = v0 ? (out + (size_t)s_tk[r0] * HD) : out;
        float* o1 = v1 ? (out + (size_t)s_tk[r1] * HD) : out;
        #pragma unroll
        for (int nb = 0; nb < 4; nb++) {
            int col = cb + nb * 8;
            if (v0) {
                atomicAdd(&o0[col],     cw0 * d[mb][nb][0]);
                atomicAdd(&o0[col + 1], cw0 * d[mb][nb][1]);
            }
            if (v1) {
                atomicAdd(&o1[col],     cw1 * d[mb][nb][2]);
                atomicAdd(&o1[col + 1], cw1 * d[mb][nb][3]);
            }
        }
    }
}

// ============================================================
extern "C" void kernel_launch(void* const* d_in, const int* in_sizes, int n_in,
                              void* d_out, int out_size) {
    const float* x    = (const float*)d_in[0];   // [T, H]
    const float* gw   = (const float*)d_in[1];   // [E, H]
    const float* bias = (const float*)d_in[2];   // [E]
    const float* w13  = (const float*)d_in[3];   // [E, 2I, H]
    const float* w2   = (const float*)d_in[4];   // [E, H, I]
    float* out = (float*)d_out;                  // [T, H]

    static int inited = 0;
    if (!inited) {
        cudaFuncSetAttribute(gemm1_mma, cudaFuncAttributeMaxDynamicSharedMemorySize, SM_G1);
        cudaFuncSetAttribute(gemm2_mma, cudaFuncAttributeMaxDynamicSharedMemorySize, SM_G2);
        inited = 1;
    }

    uint4* w13h_p; cudaGetSymbolAddress((void**)&w13h_p, d_w13h);
    uint4* w2h_p;  cudaGetSymbolAddress((void**)&w2h_p,  d_w2h);

    // 1: zero out + counts
    zero_kernel<<<2048, 256>>>((float4*)out);

    // 2,3: weight conversions
    conv_kernel<<<(NE*2*ID*(HD/8))/4/256, 256>>>((const float4*)w13, (uint4*)w13h_p, NE * 2 * ID * (HD / 8));
    conv_kernel<<<(NE*HD*(ID/8))/4/256,   256>>>((const float4*)w2,  (uint4*)w2h_p,  NE * HD * (ID / 8));

    // 4: router stage 1 — split-K logits (also converts x -> d_xh)
    dim3 rg(NT / RB, KSLICES);           // (128, 4)
    router_gemm<<<rg, 256>>>(x, gw);

    // 5: router stage 2 — topk + scatter
    topk_kernel<<<NT / 256, 256>>>(bias);

    // 6: gemm1
    dim3 g1(ID / 64, NT / 128, NE);      // (16, 32, 32)
    gemm1_mma<<<g1, 256, SM_G1>>>();

    // 7: gemm2 (combine fused via RED)
    dim3 g2(HD / 128, NT / 128, NE);     // (16, 32, 32)
    gemm2_mma<<<g2, 256, SM_G2>>>(out);
}

// round 15
// speedup vs baseline: 1.0151x; 1.0014x over previous
#include <cuda_runtime.h>
#include <cuda_fp16.h>
#include <cstdint>
#include <math.h>

#define NE 32
#define TOPK 4
#define HD 2048
#define ID 1024
#define NT 4096
#define MAXP (NT*TOPK)
#define KSLICES 4
#define KSL (HD/KSLICES)          // 512

// ---------------- scratch (static device globals) ----------------
__device__ int      d_counts[NE];
__device__ int      d_perm_tok[NE*NT];
__device__ float    d_perm_w[NE*NT];
__device__ float    d_lgpart[KSLICES*NT*NE];           // split-K partial logits, 2MB
__device__ uint32_t d_xh[NT*HD/2];                     // fp16x2, 16MB
__device__ uint32_t d_w13h[(size_t)NE*2*ID*HD/2];      // 256MB
__device__ uint32_t d_w2h[(size_t)NE*HD*ID/2];         // 128MB
__device__ uint32_t d_hh[(size_t)MAXP*ID/2];           // 32MB

// ---------------- helpers ----------------
__device__ __forceinline__ uint32_t smem_u32(const void* p) {
    uint32_t a;
    asm("{ .reg .u64 t; cvta.to.shared.u64 t, %1; cvt.u32.u64 %0, t; }" : "=r"(a) : "l"(p));
    return a;
}
__device__ __forceinline__ uint32_t f2h2(float lo, float hi) {
    uint32_t r;
    asm("cvt.rn.f16x2.f32 %0, %1, %2;" : "=r"(r) : "f"(hi), "f"(lo));
    return r;
}
__device__ __forceinline__ void cpa16(uint32_t dst, const void* src, uint32_t sz) {
    asm volatile("cp.async.cg.shared.global [%0], [%1], 16, %2;"
                 :: "r"(dst), "l"(src), "r"(sz) : "memory");
}
__device__ __forceinline__ void cpa_commit() {
    asm volatile("cp.async.commit_group;" ::: "memory");
}
__device__ __forceinline__ void cpa_wait2() {
    asm volatile("cp.async.wait_group 2;" ::: "memory");
}
__device__ __forceinline__ void ldsm4(uint32_t (&r)[4], uint32_t a) {
    asm volatile("ldmatrix.sync.aligned.m8n8.x4.shared.b16 {%0,%1,%2,%3}, [%4];"
                 : "=r"(r[0]), "=r"(r[1]), "=r"(r[2]), "=r"(r[3]) : "r"(a));
}
__device__ __forceinline__ void mma16816(float (&d)[4], const uint32_t (&a)[4],
                                         uint32_t b0, uint32_t b1) {
    asm volatile("mma.sync.aligned.m16n8k16.row.col.f32.f16.f16.f32 "
                 "{%0,%1,%2,%3}, {%4,%5,%6,%7}, {%8,%9}, {%0,%1,%2,%3};"
                 : "+f"(d[0]), "+f"(d[1]), "+f"(d[2]), "+f"(d[3])
                 : "r"(a[0]), "r"(a[1]), "r"(a[2]), "r"(a[3]), "r"(b0), "r"(b1));
}

// per-block expert base = exclusive prefix of d_counts
__device__ __forceinline__ int expert_base(int e) {
    int base = 0;
    #pragma unroll
    for (int i = 0; i < NE; i++) base += (i < e) ? d_counts[i] : 0;
    return base;
}

// ---------------- smem geometry ----------------
#define STAGES 3
#define CHB 16384                 // one tile: 128 rows x 128B (64 fp16)
#define STG_B (2*CHB)             // A + B tiles per stage
#define SM_G1 (STAGES*STG_B)              // 98304
#define SM_G2 (STAGES*STG_B + 1024)       // + cw/tok arrays

// ============================================================
// prep: one launch = conv(w13) + conv(w2) + zero(out,counts).
// Block ranges partition three independent memory-bound jobs so their
// heads/tails overlap across SMs (no inter-kernel barrier).
// ============================================================
#define C1_BLKS (NE*2*ID*(HD/8)/4/256)    // 16384
#define C2_BLKS (NE*HD*(ID/8)/4/256)      // 8192
#define ZERO_BLKS (NT*HD/4/4/256)         // 2048
#define PREP_BLKS (C1_BLKS + C2_BLKS + ZERO_BLKS)

__device__ __forceinline__ void conv_job(const float4* __restrict__ src,
                                         uint4* __restrict__ dst, int blk) {
    int i = (blk * 256 + threadIdx.x) * 4;     // exact fit
    float4 a[8];
    #pragma unroll
    for (int j = 0; j < 4; j++) {
        a[2*j]   = src[2*(i+j)];
        a[2*j+1] = src[2*(i+j)+1];
    }
    #pragma unroll
    for (int j = 0; j < 4; j++) {
        dst[i+j] = make_uint4(f2h2(a[2*j].x,   a[2*j].y),
                              f2h2(a[2*j].z,   a[2*j].w),
                              f2h2(a[2*j+1].x, a[2*j+1].y),
                              f2h2(a[2*j+1].z, a[2*j+1].w));
    }
}

__global__ void prep_kernel(const float4* __restrict__ w13,
                            const float4* __restrict__ w2,
                            float4* __restrict__ out) {
    int b = blockIdx.x;
    if (b < C1_BLKS) {
        conv_job(w13, (uint4*)d_w13h, b);
    } else if (b < C1_BLKS + C2_BLKS) {
        conv_job(w2, (uint4*)d_w2h, b - C1_BLKS);
    } else {
        int zb = b - C1_BLKS - C2_BLKS;
        int i = (zb * 256 + threadIdx.x) * 4;  // exact fit over NT*HD/4 float4
        float4 z = make_float4(0.f, 0.f, 0.f, 0.f);
        #pragma unroll
        for (int j = 0; j < 4; j++) out[i + j] = z;
        if (zb == 0 && threadIdx.x < NE) d_counts[threadIdx.x] = 0;
    }
}

// ============================================================
// router stage 1: split-K logits GEMM. grid (NT/32, KSLICES).
// ============================================================
#define RB 32
__global__ __launch_bounds__(256) void router_gemm(const float* __restrict__ x,
                                                   const float* __restrict__ gw) {
    __shared__ float xs[RB][64];
    __shared__ float gs[64][32];

    int tid = threadIdx.x;
    int t0 = blockIdx.x * RB;
    int sl = blockIdx.y;
    int k0s = sl * KSL;
    int r  = tid >> 3;
    int c8 = (tid & 7) * 8;

    int e  = tid & 31;
    int tg = tid >> 5;

    float acc0 = 0.f, acc1 = 0.f, acc2 = 0.f, acc3 = 0.f;

    for (int k0 = k0s; k0 < k0s + KSL; k0 += 64) {
        {
            const float4* p = (const float4*)(x + (size_t)(t0 + r) * HD + k0 + c8);
            float4 a = p[0], b = p[1];
            xs[r][c8+0] = a.x; xs[r][c8+1] = a.y; xs[r][c8+2] = a.z; xs[r][c8+3] = a.w;
            xs[r][c8+4] = b.x; xs[r][c8+5] = b.y; xs[r][c8+6] = b.z; xs[r][c8+7] = b.w;
            ((uint4*)d_xh)[(size_t)(t0 + r) * (HD/8) + (k0 + c8) / 8] =
                make_uint4(f2h2(a.x,a.y), f2h2(a.z,a.w), f2h2(b.x,b.y), f2h2(b.z,b.w));
        }
        {
            const float4* p = (const float4*)(gw + (size_t)r * HD + k0 + c8);
            float4 a = p[0], b = p[1];
            gs[c8+0][r] = a.x; gs[c8+1][r] = a.y; gs[c8+2][r] = a.z; gs[c8+3][r] = a.w;
            gs[c8+4][r] = b.x; gs[c8+5][r] = b.y; gs[c8+6][r] = b.z; gs[c8+7][r] = b.w;
        }
        __syncthreads();
        #pragma unroll
        for (int k = 0; k < 64; k++) {
            float g = gs[k][e];
            acc0 = fmaf(xs[tg     ][k], g, acc0);
            acc1 = fmaf(xs[tg +  8][k], g, acc1);
            acc2 = fmaf(xs[tg + 16][k], g, acc2);
            acc3 = fmaf(xs[tg + 24][k], g, acc3);
        }
        __syncthreads();
    }
    float* lp = d_lgpart + ((size_t)sl * NT + t0) * NE;
    lp[(tg     ) * NE + e] = acc0;
    lp[(tg +  8) * NE + e] = acc1;
    lp[(tg + 16) * NE + e] = acc2;
    lp[(tg + 24) * NE + e] = acc3;
}

// ============================================================
// router stage 2: sum slices, sigmoid, biased top-4, renorm, scatter.
// ============================================================
__global__ __launch_bounds__(256) void topk_kernel(const float* __restrict__ bias) {
    int t = blockIdx.x * blockDim.x + threadIdx.x;
    if (t >= NT) return;
    float sc[NE], bs[NE];
    #pragma unroll
    for (int i = 0; i < NE; i++) {
        float lg = 0.f;
        #pragma unroll
        for (int s = 0; s < KSLICES; s++)
            lg += d_lgpart[((size_t)s * NT + t) * NE + i];
        float v = 1.f / (1.f + expf(-lg));
        sc[i] = v;
        bs[i] = v + bias[i];
    }
    int idx[TOPK]; float w[TOPK]; float sum = 0.f;
    #pragma unroll
    for (int k = 0; k < TOPK; k++) {
        int bi = 0; float bv = -1e30f;
        #pragma unroll
        for (int i = 0; i < NE; i++)
            if (bs[i] > bv) { bv = bs[i]; bi = i; }
        bs[bi] = -1e30f;
        idx[k] = bi; w[k] = sc[bi]; sum += sc[bi];
    }
    float inv = 1.f / sum;
    #pragma unroll
    for (int k = 0; k < TOPK; k++) {
        int ex = idx[k];
        int pos = atomicAdd(&d_counts[ex], 1);
        d_perm_tok[ex * NT + pos] = t;
        d_perm_w[ex * NT + pos]   = w[k] * inv;
    }
}

// ============================================================
// GEMM1: gu = x_e @ w13_e^T (fp16 mma), fused SwiGLU epilogue -> d_hh (fp16)
// 256 threads, 8 warps (2x4), warp tile 64x32, 3-stage cp.async. (R11 frozen)
// ============================================================
__global__ __launch_bounds__(256, 2) void gemm1_mma() {
    int e = blockIdx.z;
    int cnt = d_counts[e];
    int m0 = blockIdx.y * 128;
    if (m0 >= cnt) return;
    int jj = blockIdx.x;                 // h-column block of 64
    int base = expert_base(e);

    extern __shared__ char sm[];
    uint32_t sb = smem_u32(sm);
    int tid = threadIdx.x;

    int fr = tid >> 1;
    int fs = (tid & 1) * 64;
    uint32_t fkey = (uint32_t)((fr & 7) << 4);
    uint32_t fdst = (uint32_t)(fr * 128);
    bool av = (m0 + fr) < cnt;
    const char* aSrc = (const char*)d_xh;
    if (av) aSrc += ((size_t)d_perm_tok[e * NT + m0 + fr] * HD) * 2 + fs;
    int wrow = ((fr & 1) ? ID : 0) + jj * 64 + (fr >> 1);   // interleave gate/up
    const char* bSrc = (const char*)d_w13h + ((size_t)(e * 2 * ID) + wrow) * HD * 2 + fs;

    int l = tid & 31, w = tid >> 5;
    int wm = w & 1, wn = w >> 1;
    uint32_t key = (uint32_t)((l & 7) << 4);
    uint32_t c0  = (uint32_t)((l >> 4) * 16);
    uint32_t aBase = (uint32_t)((wm * 64 + (l & 15)) * 128);
    uint32_t bBase = (uint32_t)(CHB + (wn * 32 + (l & 15)) * 128);

    float d[4][4][4];
    #pragma unroll
    for (int i = 0; i < 4; i++)
        #pragma unroll
        for (int j = 0; j < 4; j++)
            #pragma unroll
            for (int q = 0; q < 4; q++) d[i][j][q] = 0.f;

    const int NC = HD / 64;   // 32

    #pragma unroll
    for (int s = 0; s < STAGES; s++) {
        if (s < NC) {
            uint32_t s0 = sb + s * STG_B;
            const char* as = aSrc + s * 128;
            const char* bs = bSrc + s * 128;
            #pragma unroll
            for (int i = 0; i < 4; i++) {
                uint32_t so = (uint32_t)(fs + i * 16) ^ fkey;
                cpa16(s0 + fdst + so, as + i * 16, av ? 16 : 0);
                cpa16(s0 + CHB + fdst + so, bs + i * 16, 16);
            }
        }
        cpa_commit();
    }

    for (int c = 0; c < NC; c++) {
        cpa_wait2();
        __syncthreads();
        uint32_t s0 = sb + (c % STAGES) * STG_B;
        #pragma unroll
        for (int ks = 0; ks < 4; ks++) {
            uint32_t kb = (uint32_t)(ks * 32);
            uint32_t a[4][4], bfr[2][4];
            #pragma unroll
            for (int mb = 0; mb < 4; mb++)
                ldsm4(a[mb], s0 + aBase + mb * 2048 + ((kb + c0) ^ key));
            #pragma unroll
            for (int nb2 = 0; nb2 < 2; nb2++)
                ldsm4(bfr[nb2], s0 + bBase + nb2 * 2048 + ((kb + c0) ^ key));
            #pragma unroll
            for (int mb = 0; mb < 4; mb++)
                #pragma unroll
                for (int n = 0; n < 4; n++)
                    mma16816(d[mb][n], a[mb], bfr[n >> 1][n & 1], bfr[n >> 1][(n & 1) + 2]);
        }
        __syncthreads();
        int nc = c + STAGES;
        if (nc < NC) {
            uint32_t sf = sb + (c % STAGES) * STG_B;
            const char* as = aSrc + nc * 128;
            const char* bs = bSrc + nc * 128;
            #pragma unroll
            for (int i = 0; i < 4; i++) {
                uint32_t so = (uint32_t)(fs + i * 16) ^ fkey;
                cpa16(sf + fdst + so, as + i * 16, av ? 16 : 0);
                cpa16(sf + CHB + fdst + so, bs + i * 16, 16);
            }
        }
        cpa_commit();
    }

    __half* smh = (__half*)sm;     // 128 x 64 fp16 = 16KB (stage0 reuse, all mma done)
    int rbase = wm * 64 + (l >> 2);
    int tcol  = wn * 16 + (l & 3);
    #pragma unroll
    for (int mb = 0; mb < 4; mb++) {
        int r0 = rbase + mb * 16;
        #pragma unroll
        for (int nb = 0; nb < 4; nb++) {
            int tc = tcol + nb * 4;
            float g0 = d[mb][nb][0], u0 = d[mb][nb][1];
            float g1 = d[mb][nb][2], u1 = d[mb][nb][3];
            float h0 = g0 / (1.f + __expf(-g0)) * u0;
            float h1 = g1 / (1.f + __expf(-g1)) * u1;
            smh[r0 * 64 + tc]       = __float2half(h0);
            smh[(r0 + 8) * 64 + tc] = __float2half(h1);
        }
    }
    __syncthreads();
    int rr = tid >> 1;
    int hh = (tid & 1) * 32;
    if ((m0 + rr) < cnt) {
        const uint4* s4 = (const uint4*)((const char*)sm + (rr * 64 + hh) * 2);
        uint4* g4 = (uint4*)((char*)d_hh + (((size_t)(base + m0 + rr)) * ID + jj * 64 + hh) * 2);
        g4[0] = s4[0]; g4[1] = s4[1]; g4[2] = s4[2]; g4[3] = s4[3];
    }
}

// ============================================================
// GEMM2: y = h_e @ w2_e^T (fp16 mma); epilogue: out[tok] += cw*y via RED. (R11 frozen)
// ============================================================
__global__ __launch_bounds__(256, 2) void gemm2_mma(float* __restrict__ out) {
    int e = blockIdx.z;
    int cnt = d_counts[e];
    int m0 = blockIdx.y * 128;
    if (m0 >= cnt) return;
    int n0 = blockIdx.x * 128;
    int base = expert_base(e);

    extern __shared__ char sm[];
    uint32_t sb = smem_u32(sm);
    int tid = threadIdx.x;

    float* s_cw = (float*)(sm + STAGES * STG_B);
    int*   s_tk = (int*)(sm + STAGES * STG_B + 512);
    if (tid < 128) {
        int m = m0 + tid;
        if (m < cnt) {
            s_cw[tid] = d_perm_w[e * NT + m];
            s_tk[tid] = d_perm_tok[e * NT + m];
        }
    }

    int fr = tid >> 1;
    int fs = (tid & 1) * 64;
    uint32_t fkey = (uint32_t)((fr & 7) << 4);
    uint32_t fdst = (uint32_t)(fr * 128);
    bool av = (m0 + fr) < cnt;
    const char* aSrc = (const char*)d_hh;
    if (av) aSrc += ((size_t)(base + m0 + fr) * ID) * 2 + fs;
    const char* bSrc = (const char*)d_w2h + ((size_t)(e * HD) + n0 + fr) * ID * 2 + fs;

    int l = tid & 31, w = tid >> 5;
    int wm = w & 1, wn = w >> 1;
    uint32_t key = (uint32_t)((l & 7) << 4);
    uint32_t c0  = (uint32_t)((l >> 4) * 16);
    uint32_t aBase = (uint32_t)((wm * 64 + (l & 15)) * 128);
    uint32_t bBase = (uint32_t)(CHB + (wn * 32 + (l & 15)) * 128);

    float d[4][4][4];
    #pragma unroll
    for (int i = 0; i < 4; i++)
        #pragma unroll
        for (int j = 0; j < 4; j++)
            #pragma unroll
            for (int q = 0; q < 4; q++) d[i][j][q] = 0.f;

    const int NC = ID / 64;   // 16

    #pragma unroll
    for (int s = 0; s < STAGES; s++) {
        if (s < NC) {
            uint32_t s0 = sb + s * STG_B;
            const char* as = aSrc + s * 128;
            const char* bs = bSrc + s * 128;
            #pragma unroll
            for (int i = 0; i < 4; i++) {
                uint32_t so = (uint32_t)(fs + i * 16) ^ fkey;
                cpa16(s0 + fdst + so, as + i * 16, av ? 16 : 0);
                cpa16(s0 + CHB + fdst + so, bs + i * 16, 16);
            }
        }
        cpa_commit();
    }

    for (int c = 0; c < NC; c++) {
        cpa_wait2();
        __syncthreads();
        uint32_t s0 = sb + (c % STAGES) * STG_B;
        #pragma unroll
        for (int ks = 0; ks < 4; ks++) {
            uint32_t kb = (uint32_t)(ks * 32);
            uint32_t a[4][4], bfr[2][4];
            #pragma unroll
            for (int mb = 0; mb < 4; mb++)
                ldsm4(a[mb], s0 + aBase + mb * 2048 + ((kb + c0) ^ key));
            #pragma unroll
            for (int nb2 = 0; nb2 < 2; nb2++)
                ldsm4(bfr[nb2], s0 + bBase + nb2 * 2048 + ((kb + c0) ^ key));
            #pragma unroll
            for (int mb = 0; mb < 4; mb++)
                #pragma unroll
                for (int n = 0; n < 4; n++)
                    mma16816(d[mb][n], a[mb], bfr[n >> 1][n & 1], bfr[n >> 1][(n & 1) + 2]);
        }
        __syncthreads();
        int nc = c + STAGES;
        if (nc < NC) {
            uint32_t sf = sb + (c % STAGES) * STG_B;
            const char* as = aSrc + nc * 128;
            const char* bs = bSrc + nc * 128;
            #pragma unroll
            for (int i = 0; i < 4; i++) {
                uint32_t so = (uint32_t)(fs + i * 16) ^ fkey;
                cpa16(sf + fdst + so, as + i * 16, av ? 16 : 0);
                cpa16(sf + CHB + fdst + so, bs + i * 16, 16);
            }
        }
        cpa_commit();
    }

    // ---- epilogue: out[tok][col] += cw * y  (RED.F32, combine fused) ----
    int rbase = wm * 64 + (l >> 2);
    int cb = n0 + wn * 32 + 2 * (l & 3);
    #pragma unroll
    for (int mb = 0; mb < 4; mb++) {
        int r0 = rbase + mb * 16;
        int r1 = r0 + 8;
        bool v0 = (m0 + r0) < cnt;
        bool v1 = (m0 + r1) < cnt;
        float cw0 = v0 ? s_cw[r0] : 0.f;
        float cw1 = v1 ? s_cw[r1] : 0.f;
        float* o0 = v0 ? (out + (size_t)s_tk[r0] * HD) : out;
        float* o1 = v1 ? (out + (size_t)s_tk[r1] * HD) : out;
        #pragma unroll
        for (int nb = 0; nb < 4; nb++) {
            int col = cb + nb * 8;
            if (v0) {
                atomicAdd(&o0[col],     cw0 * d[mb][nb][0]);
                atomicAdd(&o0[col + 1], cw0 * d[mb][nb][1]);
            }
            if (v1) {
                atomicAdd(&o1[col],     cw1 * d[mb][nb][2]);
                atomicAdd(&o1[col + 1], cw1 * d[mb][nb][3]);
            }
        }
    }
}

// ============================================================
extern "C" void kernel_launch(void* const* d_in, const int* in_sizes, int n_in,
                              void* d_out, int out_size) {
    const float* x    = (const float*)d_in[0];   // [T, H]
    const float* gw   = (const float*)d_in[1];   // [E, H]
    const float* bias = (const float*)d_in[2];   // [E]
    const float* w13  = (const float*)d_in[3];   // [E, 2I, H]
    const float* w2   = (const float*)d_in[4];   // [E, H, I]
    float* out = (float*)d_out;                  // [T, H]

    static int inited = 0;
    if (!inited) {
        cudaFuncSetAttribute(gemm1_mma, cudaFuncAttributeMaxDynamicSharedMemorySize, SM_G1);
        cudaFuncSetAttribute(gemm2_mma, cudaFuncAttributeMaxDynamicSharedMemorySize, SM_G2);
        inited = 1;
    }

    // 1: prep — conv13 + conv2 + zero(out,counts), one launch
    prep_kernel<<<PREP_BLKS, 256>>>((const float4*)w13, (const float4*)w2, (float4*)out);

    // 2: router stage 1 — split-K logits (also converts x -> d_xh)
    dim3 rg(NT / RB, KSLICES);           // (128, 4)
    router_gemm<<<rg, 256>>>(x, gw);

    // 3: router stage 2 — topk + scatter
    topk_kernel<<<NT / 256, 256>>>(bias);

    // 4: gemm1
    dim3 g1(ID / 64, NT / 128, NE);      // (16, 32, 32)
    gemm1_mma<<<g1, 256, SM_G1>>>();

    // 5: gemm2 (combine fused via RED)
    dim3 g2(HD / 128, NT / 128, NE);     // (16, 32, 32)
    gemm2_mma<<<g2, 256, SM_G2>>>(out);
}

// round 16
// speedup vs baseline: 1.0178x; 1.0026x over previous
#include <cuda_runtime.h>
#include <cuda_fp16.h>
#include <cstdint>
#include <math.h>

#define NE 32
#define TOPK 4
#define HD 2048
#define ID 1024
#define NT 4096
#define MAXP (NT*TOPK)
#define KSLICES 4
#define KSL (HD/KSLICES)          // 512

// ---------------- scratch (static device globals) ----------------
__device__ int      d_counts[NE];
__device__ int      d_perm_tok[NE*NT];
__device__ float    d_perm_w[NE*NT];
__device__ float    d_lgpart[KSLICES*NT*NE];           // split-K partial logits, 2MB
__device__ uint32_t d_xh[NT*HD/2];                     // fp16x2, 16MB
__device__ uint32_t d_w13h[(size_t)NE*2*ID*HD/2];      // 256MB
__device__ uint32_t d_w2h[(size_t)NE*HD*ID/2];         // 128MB
__device__ uint32_t d_hh[(size_t)MAXP*ID/2];           // 32MB

// ---------------- helpers ----------------
__device__ __forceinline__ uint32_t smem_u32(const void* p) {
    uint32_t a;
    asm("{ .reg .u64 t; cvta.to.shared.u64 t, %1; cvt.u32.u64 %0, t; }" : "=r"(a) : "l"(p));
    return a;
}
__device__ __forceinline__ uint32_t f2h2(float lo, float hi) {
    uint32_t r;
    asm("cvt.rn.f16x2.f32 %0, %1, %2;" : "=r"(r) : "f"(hi), "f"(lo));
    return r;
}
__device__ __forceinline__ void cpa16(uint32_t dst, const void* src, uint32_t sz) {
    asm volatile("cp.async.cg.shared.global [%0], [%1], 16, %2;"
                 :: "r"(dst), "l"(src), "r"(sz) : "memory");
}
__device__ __forceinline__ void cpa_commit() {
    asm volatile("cp.async.commit_group;" ::: "memory");
}
__device__ __forceinline__ void cpa_wait2() {
    asm volatile("cp.async.wait_group 2;" ::: "memory");
}
__device__ __forceinline__ void ldsm4(uint32_t (&r)[4], uint32_t a) {
    asm volatile("ldmatrix.sync.aligned.m8n8.x4.shared.b16 {%0,%1,%2,%3}, [%4];"
                 : "=r"(r[0]), "=r"(r[1]), "=r"(r[2]), "=r"(r[3]) : "r"(a));
}
__device__ __forceinline__ void mma16816(float (&d)[4], const uint32_t (&a)[4],
                                         uint32_t b0, uint32_t b1) {
    asm volatile("mma.sync.aligned.m16n8k16.row.col.f32.f16.f16.f32 "
                 "{%0,%1,%2,%3}, {%4,%5,%6,%7}, {%8,%9}, {%0,%1,%2,%3};"
                 : "+f"(d[0]), "+f"(d[1]), "+f"(d[2]), "+f"(d[3])
                 : "r"(a[0]), "r"(a[1]), "r"(a[2]), "r"(a[3]), "r"(b0), "r"(b1));
}

// per-block expert base = exclusive prefix of d_counts
__device__ __forceinline__ int expert_base(int e) {
    int base = 0;
    #pragma unroll
    for (int i = 0; i < NE; i++) base += (i < e) ? d_counts[i] : 0;
    return base;
}

// ---------------- smem geometry ----------------
#define STAGES 3
#define CHB 16384                 // one tile: 128 rows x 128B (64 fp16)
#define STG_B (2*CHB)             // A + B tiles per stage
#define SM_G1 (STAGES*STG_B)              // 98304
#define SM_G2 (STAGES*STG_B + 1024)       // + cw/tok arrays

// ============================================================
// fused prep: router split-K (blocks 0..511, FIRST so they co-run with the
// DRAM-bound conversions) + conv(w13) + conv(w2) + zero(out,counts).
// ============================================================
#define RB 32
#define R_BLKS ((NT/RB)*KSLICES)          // 512
#define C1_BLKS (NE*2*ID*(HD/8)/4/256)    // 16384
#define C2_BLKS (NE*HD*(ID/8)/4/256)      // 8192
#define ZERO_BLKS (NT*HD/4/4/256)         // 2048
#define PREP_BLKS (R_BLKS + C1_BLKS + C2_BLKS + ZERO_BLKS)

__device__ __forceinline__ void conv_job(const float4* __restrict__ src,
                                         uint4* __restrict__ dst, int blk) {
    int i = (blk * 256 + threadIdx.x) * 4;     // exact fit
    float4 a[8];
    #pragma unroll
    for (int j = 0; j < 4; j++) {
        a[2*j]   = src[2*(i+j)];
        a[2*j+1] = src[2*(i+j)+1];
    }
    #pragma unroll
    for (int j = 0; j < 4; j++) {
        dst[i+j] = make_uint4(f2h2(a[2*j].x,   a[2*j].y),
                              f2h2(a[2*j].z,   a[2*j].w),
                              f2h2(a[2*j+1].x, a[2*j+1].y),
                              f2h2(a[2*j+1].z, a[2*j+1].w));
    }
}

__device__ void router_job(const float* __restrict__ x,
                           const float* __restrict__ gw, int blk) {
    __shared__ float xs[RB][64];
    __shared__ float gs[64][32];

    int tid = threadIdx.x;
    int t0 = (blk & (NT/RB - 1)) * RB;
    int sl = blk >> 7;                 // NT/RB = 128
    int k0s = sl * KSL;
    int r  = tid >> 3;
    int c8 = (tid & 7) * 8;

    int e  = tid & 31;
    int tg = tid >> 5;

    float acc0 = 0.f, acc1 = 0.f, acc2 = 0.f, acc3 = 0.f;

    for (int k0 = k0s; k0 < k0s + KSL; k0 += 64) {
        {
            const float4* p = (const float4*)(x + (size_t)(t0 + r) * HD + k0 + c8);
            float4 a = p[0], b = p[1];
            xs[r][c8+0] = a.x; xs[r][c8+1] = a.y; xs[r][c8+2] = a.z; xs[r][c8+3] = a.w;
            xs[r][c8+4] = b.x; xs[r][c8+5] = b.y; xs[r][c8+6] = b.z; xs[r][c8+7] = b.w;
            ((uint4*)d_xh)[(size_t)(t0 + r) * (HD/8) + (k0 + c8) / 8] =
                make_uint4(f2h2(a.x,a.y), f2h2(a.z,a.w), f2h2(b.x,b.y), f2h2(b.z,b.w));
        }
        {
            const float4* p = (const float4*)(gw + (size_t)r * HD + k0 + c8);
            float4 a = p[0], b = p[1];
            gs[c8+0][r] = a.x; gs[c8+1][r] = a.y; gs[c8+2][r] = a.z; gs[c8+3][r] = a.w;
            gs[c8+4][r] = b.x; gs[c8+5][r] = b.y; gs[c8+6][r] = b.z; gs[c8+7][r] = b.w;
        }
        __syncthreads();
        #pragma unroll
        for (int k = 0; k < 64; k++) {
            float g = gs[k][e];
            acc0 = fmaf(xs[tg     ][k], g, acc0);
            acc1 = fmaf(xs[tg +  8][k], g, acc1);
            acc2 = fmaf(xs[tg + 16][k], g, acc2);
            acc3 = fmaf(xs[tg + 24][k], g, acc3);
        }
        __syncthreads();
    }
    float* lp = d_lgpart + ((size_t)sl * NT + t0) * NE;
    lp[(tg     ) * NE + e] = acc0;
    lp[(tg +  8) * NE + e] = acc1;
    lp[(tg + 16) * NE + e] = acc2;
    lp[(tg + 24) * NE + e] = acc3;
}

__global__ void prep_kernel(const float* __restrict__ x,
                            const float* __restrict__ gw,
                            const float4* __restrict__ w13,
                            const float4* __restrict__ w2,
                            float4* __restrict__ out) {
    int b = blockIdx.x;
    if (b < R_BLKS) {
        router_job(x, gw, b);
    } else if (b < R_BLKS + C1_BLKS) {
        conv_job(w13, (uint4*)d_w13h, b - R_BLKS);
    } else if (b < R_BLKS + C1_BLKS + C2_BLKS) {
        conv_job(w2, (uint4*)d_w2h, b - R_BLKS - C1_BLKS);
    } else {
        int zb = b - R_BLKS - C1_BLKS - C2_BLKS;
        int i = (zb * 256 + threadIdx.x) * 4;  // exact fit over NT*HD/4 float4
        float4 z = make_float4(0.f, 0.f, 0.f, 0.f);
        #pragma unroll
        for (int j = 0; j < 4; j++) out[i + j] = z;
        if (zb == 0 && threadIdx.x < NE) d_counts[threadIdx.x] = 0;
    }
}

// ============================================================
// router stage 2: sum slices, sigmoid, biased top-4, renorm, scatter.
// ============================================================
__global__ __launch_bounds__(256) void topk_kernel(const float* __restrict__ bias) {
    int t = blockIdx.x * blockDim.x + threadIdx.x;
    if (t >= NT) return;
    float sc[NE], bs[NE];
    #pragma unroll
    for (int i = 0; i < NE; i++) {
        float lg = 0.f;
        #pragma unroll
        for (int s = 0; s < KSLICES; s++)
            lg += d_lgpart[((size_t)s * NT + t) * NE + i];
        float v = 1.f / (1.f + expf(-lg));
        sc[i] = v;
        bs[i] = v + bias[i];
    }
    int idx[TOPK]; float w[TOPK]; float sum = 0.f;
    #pragma unroll
    for (int k = 0; k < TOPK; k++) {
        int bi = 0; float bv = -1e30f;
        #pragma unroll
        for (int i = 0; i < NE; i++)
            if (bs[i] > bv) { bv = bs[i]; bi = i; }
        bs[bi] = -1e30f;
        idx[k] = bi; w[k] = sc[bi]; sum += sc[bi];
    }
    float inv = 1.f / sum;
    #pragma unroll
    for (int k = 0; k < TOPK; k++) {
        int ex = idx[k];
        int pos = atomicAdd(&d_counts[ex], 1);
        d_perm_tok[ex * NT + pos] = t;
        d_perm_w[ex * NT + pos]   = w[k] * inv;
    }
}

// ============================================================
// GEMM1: gu = x_e @ w13_e^T (fp16 mma), fused SwiGLU epilogue -> d_hh (fp16)
// 256 threads, 8 warps (2x4), warp tile 64x32, 3-stage cp.async. (R11 frozen)
// ============================================================
__global__ __launch_bounds__(256, 2) void gemm1_mma() {
    int e = blockIdx.z;
    int cnt = d_counts[e];
    int m0 = blockIdx.y * 128;
    if (m0 >= cnt) return;
    int jj = blockIdx.x;                 // h-column block of 64
    int base = expert_base(e);

    extern __shared__ char sm[];
    uint32_t sb = smem_u32(sm);
    int tid = threadIdx.x;

    int fr = tid >> 1;
    int fs = (tid & 1) * 64;
    uint32_t fkey = (uint32_t)((fr & 7) << 4);
    uint32_t fdst = (uint32_t)(fr * 128);
    bool av = (m0 + fr) < cnt;
    const char* aSrc = (const char*)d_xh;
    if (av) aSrc += ((size_t)d_perm_tok[e * NT + m0 + fr] * HD) * 2 + fs;
    int wrow = ((fr & 1) ? ID : 0) + jj * 64 + (fr >> 1);   // interleave gate/up
    const char* bSrc = (const char*)d_w13h + ((size_t)(e * 2 * ID) + wrow) * HD * 2 + fs;

    int l = tid & 31, w = tid >> 5;
    int wm = w & 1, wn = w >> 1;
    uint32_t key = (uint32_t)((l & 7) << 4);
    uint32_t c0  = (uint32_t)((l >> 4) * 16);
    uint32_t aBase = (uint32_t)((wm * 64 + (l & 15)) * 128);
    uint32_t bBase = (uint32_t)(CHB + (wn * 32 + (l & 15)) * 128);

    float d[4][4][4];
    #pragma unroll
    for (int i = 0; i < 4; i++)
        #pragma unroll
        for (int j = 0; j < 4; j++)
            #pragma unroll
            for (int q = 0; q < 4; q++) d[i][j][q] = 0.f;

    const int NC = HD / 64;   // 32

    #pragma unroll
    for (int s = 0; s < STAGES; s++) {
        if (s < NC) {
            uint32_t s0 = sb + s * STG_B;
            const char* as = aSrc + s * 128;
            const char* bs = bSrc + s * 128;
            #pragma unroll
            for (int i = 0; i < 4; i++) {
                uint32_t so = (uint32_t)(fs + i * 16) ^ fkey;
                cpa16(s0 + fdst + so, as + i * 16, av ? 16 : 0);
                cpa16(s0 + CHB + fdst + so, bs + i * 16, 16);
            }
        }
        cpa_commit();
    }

    for (int c = 0; c < NC; c++) {
        cpa_wait2();
        __syncthreads();
        uint32_t s0 = sb + (c % STAGES) * STG_B;
        #pragma unroll
        for (int ks = 0; ks < 4; ks++) {
            uint32_t kb = (uint32_t)(ks * 32);
            uint32_t a[4][4], bfr[2][4];
            #pragma unroll
            for (int mb = 0; mb < 4; mb++)
                ldsm4(a[mb], s0 + aBase + mb * 2048 + ((kb + c0) ^ key));
            #pragma unroll
            for (int nb2 = 0; nb2 < 2; nb2++)
                ldsm4(bfr[nb2], s0 + bBase + nb2 * 2048 + ((kb + c0) ^ key));
            #pragma unroll
            for (int mb = 0; mb < 4; mb++)
                #pragma unroll
                for (int n = 0; n < 4; n++)
                    mma16816(d[mb][n], a[mb], bfr[n >> 1][n & 1], bfr[n >> 1][(n & 1) + 2]);
        }
        __syncthreads();
        int nc = c + STAGES;
        if (nc < NC) {
            uint32_t sf = sb + (c % STAGES) * STG_B;
            const char* as = aSrc + nc * 128;
            const char* bs = bSrc + nc * 128;
            #pragma unroll
            for (int i = 0; i < 4; i++) {
                uint32_t so = (uint32_t)(fs + i * 16) ^ fkey;
                cpa16(sf + fdst + so, as + i * 16, av ? 16 : 0);
                cpa16(sf + CHB + fdst + so, bs + i * 16, 16);
            }
        }
        cpa_commit();
    }

    __half* smh = (__half*)sm;     // 128 x 64 fp16 = 16KB (stage0 reuse, all mma done)
    int rbase = wm * 64 + (l >> 2);
    int tcol  = wn * 16 + (l & 3);
    #pragma unroll
    for (int mb = 0; mb < 4; mb++) {
        int r0 = rbase + mb * 16;
        #pragma unroll
        for (int nb = 0; nb < 4; nb++) {
            int tc = tcol + nb * 4;
            float g0 = d[mb][nb][0], u0 = d[mb][nb][1];
            float g1 = d[mb][nb][2], u1 = d[mb][nb][3];
            float h0 = g0 / (1.f + __expf(-g0)) * u0;
            float h1 = g1 / (1.f + __expf(-g1)) * u1;
            smh[r0 * 64 + tc]       = __float2half(h0);
            smh[(r0 + 8) * 64 + tc] = __float2half(h1);
        }
    }
    __syncthreads();
    int rr = tid >> 1;
    int hh = (tid & 1) * 32;
    if ((m0 + rr) < cnt) {
        const uint4* s4 = (const uint4*)((const char*)sm + (rr * 64 + hh) * 2);
        uint4* g4 = (uint4*)((char*)d_hh + (((size_t)(base + m0 + rr)) * ID + jj * 64 + hh) * 2);
        g4[0] = s4[0]; g4[1] = s4[1]; g4[2] = s4[2]; g4[3] = s4[3];
    }
}

// ============================================================
// GEMM2: y = h_e @ w2_e^T (fp16 mma); epilogue: out[tok] += cw*y via RED. (R11 frozen)
// ============================================================
__global__ __launch_bounds__(256, 2) void gemm2_mma(float* __restrict__ out) {
    int e = blockIdx.z;
    int cnt = d_counts[e];
    int m0 = blockIdx.y * 128;
    if (m0 >= cnt) return;
    int n0 = blockIdx.x * 128;
    int base = expert_base(e);

    extern __shared__ char sm[];
    uint32_t sb = smem_u32(sm);
    int tid = threadIdx.x;

    float* s_cw = (float*)(sm + STAGES * STG_B);
    int*   s_tk = (int*)(sm + STAGES * STG_B + 512);
    if (tid < 128) {
        int m = m0 + tid;
        if (m < cnt) {
            s_cw[tid] = d_perm_w[e * NT + m];
            s_tk[tid] = d_perm_tok[e * NT + m];
        }
    }

    int fr = tid >> 1;
    int fs = (tid & 1) * 64;
    uint32_t fkey = (uint32_t)((fr & 7) << 4);
    uint32_t fdst = (uint32_t)(fr * 128);
    bool av = (m0 + fr) < cnt;
    const char* aSrc = (const char*)d_hh;
    if (av) aSrc += ((size_t)(base + m0 + fr) * ID) * 2 + fs;
    const char* bSrc = (const char*)d_w2h + ((size_t)(e * HD) + n0 + fr) * ID * 2 + fs;

    int l = tid & 31, w = tid >> 5;
    int wm = w & 1, wn = w >> 1;
    uint32_t key = (uint32_t)((l & 7) << 4);
    uint32_t c0  = (uint32_t)((l >> 4) * 16);
    uint32_t aBase = (uint32_t)((wm * 64 + (l & 15)) * 128);
    uint32_t bBase = (uint32_t)(CHB + (wn * 32 + (l & 15)) * 128);

    float d[4][4][4];
    #pragma unroll
    for (int i = 0; i < 4; i++)
        #pragma unroll
        for (int j = 0; j < 4; j++)
            #pragma unroll
            for (int q = 0; q < 4; q++) d[i][j][q] = 0.f;

    const int NC = ID / 64;   // 16

    #pragma unroll
    for (int s = 0; s < STAGES; s++) {
        if (s < NC) {
            uint32_t s0 = sb + s * STG_B;
            const char* as = aSrc + s * 128;
            const char* bs = bSrc + s * 128;
            #pragma unroll
            for (int i = 0; i < 4; i++) {
                uint32_t so = (uint32_t)(fs + i * 16) ^ fkey;
                cpa16(s0 + fdst + so, as + i * 16, av ? 16 : 0);
                cpa16(s0 + CHB + fdst + so, bs + i * 16, 16);
            }
        }
        cpa_commit();
    }

    for (int c = 0; c < NC; c++) {
        cpa_wait2();
        __syncthreads();
        uint32_t s0 = sb + (c % STAGES) * STG_B;
        #pragma unroll
        for (int ks = 0; ks < 4; ks++) {
            uint32_t kb = (uint32_t)(ks * 32);
            uint32_t a[4][4], bfr[2][4];
            #pragma unroll
            for (int mb = 0; mb < 4; mb++)
                ldsm4(a[mb], s0 + aBase + mb * 2048 + ((kb + c0) ^ key));
            #pragma unroll
            for (int nb2 = 0; nb2 < 2; nb2++)
                ldsm4(bfr[nb2], s0 + bBase + nb2 * 2048 + ((kb + c0) ^ key));
            #pragma unroll
            for (int mb = 0; mb < 4; mb++)
                #pragma unroll
                for (int n = 0; n < 4; n++)
                    mma16816(d[mb][n], a[mb], bfr[n >> 1][n & 1], bfr[n >> 1][(n & 1) + 2]);
        }
        __syncthreads();
        int nc = c + STAGES;
        if (nc < NC) {
            uint32_t sf = sb + (c % STAGES) * STG_B;
            const char* as = aSrc + nc * 128;
            const char* bs = bSrc + nc * 128;
            #pragma unroll
            for (int i = 0; i < 4; i++) {
                uint32_t so = (uint32_t)(fs + i * 16) ^ fkey;
                cpa16(sf + fdst + so, as + i * 16, av ? 16 : 0);
                cpa16(sf + CHB + fdst + so, bs + i * 16, 16);
            }
        }
        cpa_commit();
    }

    // ---- epilogue: out[tok][col] += cw * y  (RED.F32, combine fused) ----
    int rbase = wm * 64 + (l >> 2);
    int cb = n0 + wn * 32 + 2 * (l & 3);
    #pragma unroll
    for (int mb = 0; mb < 4; mb++) {
        int r0 = rbase + mb * 16;
        int r1 = r0 + 8;
        bool v0 = (m0 + r0) < cnt;
        bool v1 = (m0 + r1) < cnt;
        float cw0 = v0 ? s_cw[r0] : 0.f;
        float cw1 = v1 ? s_cw[r1] : 0.f;
        float* o0 = v0 ? (out + (size_t)s_tk[r0] * HD) : out;
        float* o1 = v1 ? (out + (size_t)s_tk[r1] * HD) : out;
        #pragma unroll
        for (int nb = 0; nb < 4; nb++) {
            int col = cb + nb * 8;
            if (v0) {
                atomicAdd(&o0[col],     cw0 * d[mb][nb][0]);
                atomicAdd(&o0[col + 1], cw0 * d[mb][nb][1]);
            }
            if (v1) {
                atomicAdd(&o1[col],     cw1 * d[mb][nb][2]);
                atomicAdd(&o1[col + 1], cw1 * d[mb][nb][3]);
            }
        }
    }
}

// ============================================================
extern "C" void kernel_launch(void* const* d_in, const int* in_sizes, int n_in,
                              void* d_out, int out_size) {
    const float* x    = (const float*)d_in[0];   // [T, H]
    const float* gw   = (const float*)d_in[1];   // [E, H]
    const float* bias = (const float*)d_in[2];   // [E]
    const float* w13  = (const float*)d_in[3];   // [E, 2I, H]
    const float* w2   = (const float*)d_in[4];   // [E, H, I]
    float* out = (float*)d_out;                  // [T, H]

    static int inited = 0;
    if (!inited) {
        cudaFuncSetAttribute(gemm1_mma, cudaFuncAttributeMaxDynamicSharedMemorySize, SM_G1);
        cudaFuncSetAttribute(gemm2_mma, cudaFuncAttributeMaxDynamicSharedMemorySize, SM_G2);
        inited = 1;
    }

    // 1: fused prep — router split-K + conv13 + conv2 + zero, one launch
    prep_kernel<<<PREP_BLKS, 256>>>(x, gw, (const float4*)w13, (const float4*)w2, (float4*)out);

    // 2: topk + scatter
    topk_kernel<<<NT / 256, 256>>>(bias);

    // 3: gemm1
    dim3 g1(ID / 64, NT / 128, NE);      // (16, 32, 32)
    gemm1_mma<<<g1, 256, SM_G1>>>();

    // 4: gemm2 (combine fused via RED)
    dim3 g2(HD / 128, NT / 128, NE);     // (16, 32, 32)
    gemm2_mma<<<g2, 256, SM_G2>>>(out);
}